// round 1
// baseline (speedup 1.0000x reference)
#include <cuda_runtime.h>

// FullFixedTimeCausalConstructiveAttention
// B=8, L=1024, H=8, E=64, HIST=512 (read from device), causal.
//
// Flash-attention style, fp32. One thread owns one query row:
//   - q_eff row (64 f32) in registers
//   - O accumulator (64 f32) in registers
//   - K/V tiles (64 rows x 64) staged in smem, broadcast LDS.128 reads
//   - online softmax processed in 16-key chunks (sv[16] in regs)
// Diagonal replacement (l>=hist) and the values-delta epilogue handled inline.

#define BQ 128      // query rows per CTA (== threads)
#define BK 64       // key rows per smem tile
#define NTHREADS 128
#define B_ 8
#define L_ 1024
#define H_ 8
#define E_ 64

__global__ __launch_bounds__(NTHREADS, 2)
void ffcca_kernel(const float* __restrict__ Q, const float* __restrict__ K,
                  const float* __restrict__ V, const float* __restrict__ Qd,
                  const float* __restrict__ Kd, const float* __restrict__ Vd,
                  const int* __restrict__ histp, float* __restrict__ Out)
{
    const int hist = *histp;                 // 512
    const int bh = blockIdx.y;               // 0..63
    const int b  = bh >> 3;
    const int h  = bh & 7;
    const int m0 = blockIdx.x * BQ;
    const int t  = threadIdx.x;
    const int l  = m0 + t;                   // this thread's query row

    __shared__ float4 Ks[BK][E_/4];
    __shared__ float4 Vs[BK][E_/4];

    const size_t rowstride = (size_t)H_ * E_;               // floats between consecutive l
    const size_t base_bh   = (size_t)b * L_ * rowstride + (size_t)h * E_;

    // ---- load q_eff row (queries for l<hist, queries_drawn for l>=hist) ----
    const float* qsrc = (l < hist) ? Q : Qd;
    const float4* qrow = (const float4*)(qsrc + base_bh + (size_t)l * rowstride);
    float4 qr[16];
    #pragma unroll
    for (int i = 0; i < 16; i++) qr[i] = qrow[i];

    // ---- diagonal replacement score: q_eff[l] . keys_drawn[l]  (l>=hist only) ----
    float diag_s = 0.f;
    if (l >= hist) {
        const float4* kdr = (const float4*)(Kd + base_bh + (size_t)l * rowstride);
        #pragma unroll
        for (int i = 0; i < 16; i++) {
            float4 x = kdr[i];
            diag_s += qr[i].x*x.x + qr[i].y*x.y + qr[i].z*x.z + qr[i].w*x.w;
        }
    }

    float mrun = -1e30f, drun = 0.f;
    float4 acc[16];
    #pragma unroll
    for (int i = 0; i < 16; i++) acc[i] = make_float4(0.f, 0.f, 0.f, 0.f);

    const float scale = 0.125f;              // 1/sqrt(64)
    const int n_end = m0 + BQ;               // keys needed: s <= max row in this CTA

    for (int n0 = 0; n0 < n_end; n0 += BK) {
        // ---- cooperative K/V tile load: BK*E floats each = 1024 float4 per tensor ----
        const float4* kb = (const float4*)(K + base_bh + (size_t)n0 * rowstride);
        const float4* vb = (const float4*)(V + base_bh + (size_t)n0 * rowstride);
        #pragma unroll
        for (int i = 0; i < 8; i++) {
            int idx = t + i * NTHREADS;      // 0..1023
            int j = idx >> 4;                // key row in tile
            int c = idx & 15;                // float4 column
            Ks[j][c] = kb[(size_t)j * (rowstride / 4) + c];
            Vs[j][c] = vb[(size_t)j * (rowstride / 4) + c];
        }
        __syncthreads();

        if (n0 <= l) {                       // this row needs at least one key in this tile
            #pragma unroll 1
            for (int jc = 0; jc < BK; jc += 16) {
                // ---- scores for 16 keys ----
                float sv[16];
                float cm = -1e30f;
                #pragma unroll
                for (int jj = 0; jj < 16; jj++) {
                    const int s = n0 + jc + jj;
                    float dot = 0.f;
                    #pragma unroll
                    for (int i = 0; i < 16; i++) {
                        float4 x = Ks[jc + jj][i];
                        dot += qr[i].x*x.x + qr[i].y*x.y + qr[i].z*x.z + qr[i].w*x.w;
                    }
                    if (s == l && l >= hist) dot = diag_s;   // diagonal replacement
                    float sc = (s <= l) ? dot * scale : -1e30f;  // causal mask
                    sv[jj] = sc;
                    cm = fmaxf(cm, sc);
                }
                // ---- online softmax rescale (skip when max unchanged) ----
                if (cm > mrun) {
                    float cf = __expf(mrun - cm);
                    mrun = cm;
                    drun *= cf;
                    #pragma unroll
                    for (int i = 0; i < 16; i++) {
                        acc[i].x *= cf; acc[i].y *= cf; acc[i].z *= cf; acc[i].w *= cf;
                    }
                }
                // ---- accumulate P.V ----
                #pragma unroll
                for (int jj = 0; jj < 16; jj++) {
                    float p = __expf(sv[jj] - mrun);         // 0 for masked (-1e30)
                    drun += p;
                    #pragma unroll
                    for (int i = 0; i < 16; i++) {
                        float4 x = Vs[jc + jj][i];
                        acc[i].x += p*x.x; acc[i].y += p*x.y;
                        acc[i].z += p*x.z; acc[i].w += p*x.w;
                    }
                }
            }
        }
        __syncthreads();
    }

    // ---- epilogue ----
    const float invd = 1.f / drun;
    float4* orow = (float4*)(Out + base_bh + (size_t)l * rowstride);
    if (l >= hist) {
        const float diagA = __expf(diag_s * scale - mrun) * invd;
        const float4* vr  = (const float4*)(V  + base_bh + (size_t)l * rowstride);
        const float4* vdr = (const float4*)(Vd + base_bh + (size_t)l * rowstride);
        #pragma unroll
        for (int i = 0; i < 16; i++) {
            float4 a = acc[i], x = vr[i], y = vdr[i];
            float4 o;
            o.x = a.x * invd + diagA * (y.x - x.x);
            o.y = a.y * invd + diagA * (y.y - x.y);
            o.z = a.z * invd + diagA * (y.z - x.z);
            o.w = a.w * invd + diagA * (y.w - x.w);
            orow[i] = o;
        }
    } else {
        #pragma unroll
        for (int i = 0; i < 16; i++) {
            float4 a = acc[i];
            orow[i] = make_float4(a.x*invd, a.y*invd, a.z*invd, a.w*invd);
        }
    }
}

extern "C" void kernel_launch(void* const* d_in, const int* in_sizes, int n_in,
                              void* d_out, int out_size) {
    const float* Q  = (const float*)d_in[0];   // queries
    const float* K  = (const float*)d_in[1];   // keys
    const float* V  = (const float*)d_in[2];   // values
    const float* Qd = (const float*)d_in[3];   // queries_drawn
    const float* Kd = (const float*)d_in[4];   // keys_drawn
    const float* Vd = (const float*)d_in[5];   // values_drawn
    // d_in[6] = attn_mask (deterministic causal triu, implemented analytically)
    const int* histp = (const int*)d_in[7];    // history_len
    dim3 grid(L_ / BQ, B_ * H_);
    ffcca_kernel<<<grid, NTHREADS>>>(Q, K, V, Qd, Kd, Vd, histp, (float*)d_out);
}